// round 15
// baseline (speedup 1.0000x reference)
#include <cuda_runtime.h>
#include <cuda_bf16.h>
#include <cuda_fp16.h>
#include <mma.h>
#include <math.h>

using namespace nvcuda;

// Problem-size constants (from reference setup_inputs)
#define N_MAX   100000
#define E_MAX   1600000
#define PAD_ROWS 128
#define CSR_BLOCKS 148

// ------------------------- device scratch (static, no allocs) ---------------
__device__ int   g_deg[N_MAX];
__device__ int   g_rowptr[N_MAX + 1];
__device__ int   g_epos[N_MAX];
__device__ int2  g_epk[E_MAX];                          // packed (src, weight-bits)
__device__ __half g_sup1h[(N_MAX + PAD_ROWS) * 128];    // fp16 support1 (25.6 MB)
__device__ __half g_sup2h[(N_MAX + PAD_ROWS) * 64];     // fp16 support2 (12.8 MB)
__device__ int   g_partials[256];
__device__ int   g_bar_cnt = 0;
__device__ int   g_bar_gen = 0;

// ---------------------- manual grid barrier (gen-counting) -------------------
__device__ __forceinline__ void grid_bar() {
    __syncthreads();
    if (threadIdx.x == 0) {
        int gen = *(volatile int*)&g_bar_gen;
        __threadfence();                       // order gen-read before arrive
        int t = atomicAdd(&g_bar_cnt, 1);
        if (t == CSR_BLOCKS - 1) {
            atomicExch(&g_bar_cnt, 0);
            __threadfence();
            atomicAdd(&g_bar_gen, 1);          // release
        } else {
            while (*(volatile int*)&g_bar_gen == gen) __nanosleep(64);
        }
        __threadfence();                       // acquire
    }
    __syncthreads();
}

// ------------- fused CSR build: zero + hist + scan(3 lvl) + scatter ----------
__global__ void __launch_bounds__(256)
csr_fused_k(const int* __restrict__ src, const int* __restrict__ dst,
            const float* __restrict__ w, int E, int N, int nchunk) {
    __shared__ int sh[256];
    const int tid = threadIdx.x;
    const int gid = blockIdx.x * 256 + tid;
    const int nth = CSR_BLOCKS * 256;

    // ---- phase 0: zero degrees ----
    for (int i = gid; i < N; i += nth) g_deg[i] = 0;
    grid_bar();

    // ---- phase 1: histogram (int4 vectorized) ----
    {
        int E4 = E >> 2;
        const int4* d4 = (const int4*)dst;
        for (int e = gid; e < E4; e += nth) {
            int4 d = __ldcs(&d4[e]);
            atomicAdd(&g_deg[d.x], 1);
            atomicAdd(&g_deg[d.y], 1);
            atomicAdd(&g_deg[d.z], 1);
            atomicAdd(&g_deg[d.w], 1);
        }
        if (gid == 0)
            for (int i = E4 * 4; i < E; i++) atomicAdd(&g_deg[dst[i]], 1);
    }
    grid_bar();

    // ---- phase 2: per-1024-chunk partial sums ----
    if (blockIdx.x < nchunk) {
        int base = blockIdx.x * 1024 + tid * 4;
        int s = 0;
#pragma unroll
        for (int j = 0; j < 4; j++) { int idx = base + j; if (idx < N) s += g_deg[idx]; }
        sh[tid] = s;
        __syncthreads();
        for (int off = 128; off > 0; off >>= 1) {
            if (tid < off) sh[tid] += sh[tid + off];
            __syncthreads();
        }
        if (tid == 0) g_partials[blockIdx.x] = sh[0];
    }
    grid_bar();

    // ---- phase 3: exclusive scan of chunk partials (block 0) ----
    if (blockIdx.x == 0) {
        int v = (tid < nchunk) ? g_partials[tid] : 0;
        sh[tid] = v;
        __syncthreads();
        for (int off = 1; off < 256; off <<= 1) {
            int x = (tid >= off) ? sh[tid - off] : 0;
            __syncthreads();
            sh[tid] += x;
            __syncthreads();
        }
        if (tid < nchunk) g_partials[tid] = sh[tid] - v;
        if (tid == 255) g_rowptr[N] = sh[255];
    }
    grid_bar();

    // ---- phase 4: final exclusive scan within chunks -> rowptr + epos ----
    if (blockIdx.x < nchunk) {
        int base = blockIdx.x * 1024 + tid * 4;
        int v[4]; int tsum = 0;
#pragma unroll
        for (int j = 0; j < 4; j++) { v[j] = (base + j < N) ? g_deg[base + j] : 0; tsum += v[j]; }
        sh[tid] = tsum;
        __syncthreads();
        for (int off = 1; off < 256; off <<= 1) {
            int x = (tid >= off) ? sh[tid - off] : 0;
            __syncthreads();
            sh[tid] += x;
            __syncthreads();
        }
        int run = g_partials[blockIdx.x] + (sh[tid] - tsum);
#pragma unroll
        for (int j = 0; j < 4; j++) {
            int idx = base + j;
            if (idx < N) { g_rowptr[idx] = run; g_epos[idx] = run; }
            run += v[j];
        }
    }
    grid_bar();

    // ---- phase 5: scatter edges into dst-grouped list ----
    for (int e = gid; e < E; e += nth) {
        int d  = __ldcs(&dst[e]);
        int s  = __ldcs(&src[e]);
        float ww = __ldcs(&w[e]);
        int p = atomicAdd(&g_epos[d], 1);
        g_epk[p] = make_int2(s, __float_as_int(ww));
    }
}

// ---------------- wmma GEMM1: Ch[M,128] = fp16(A[M,256] @ W1) ---------------
template <int BN, int K>
__global__ void __launch_bounds__(256)
gemm_wmma_k(const float* __restrict__ A,
            const float* __restrict__ W,
            __half* __restrict__ Ch, int M) {
    constexpr int CK   = 32;
    constexpr int NCH  = K / CK;
    constexpr int NF   = BN / 32;
    constexpr int WU   = BN / 32;
    constexpr int APAD = 40;
    constexpr int BPAD = BN + 8;
    constexpr int A_ELE = 128 * APAD;
    constexpr int POOL  = (A_ELE + 32 * BPAD) * 2 + 11264;

    __shared__ __align__(32) char pool[POOL];
    __half* sA = (__half*)pool;
    __half* sB = sA + A_ELE;
    float* sStage = (float*)pool;

    const int tid    = threadIdx.x;
    const int wid    = tid >> 5;
    const int lane   = tid & 31;
    const int warp_m = wid >> 1;
    const int warp_n = wid & 1;
    const int m0     = blockIdx.x * 128;

    wmma::fragment<wmma::accumulator, 16, 16, 16, float> acc[2][NF];
#pragma unroll
    for (int i = 0; i < 2; i++)
#pragma unroll
        for (int j = 0; j < NF; j++) wmma::fill_fragment(acc[i][j], 0.0f);

    float4 pf[4];
#pragma unroll
    for (int u = 0; u < 4; u++) {
        int slot = tid + u * 256;
        int r = slot >> 3, c4 = slot & 7;
        int m = m0 + r;
        pf[u] = (m < M) ? __ldcs((const float4*)&A[(size_t)m * K + c4 * 4])
                        : make_float4(0.f, 0.f, 0.f, 0.f);
    }

    for (int ch = 0; ch < NCH; ch++) {
        const int k0 = ch * CK;
        float4 rw[WU];
        {
            const float4* srcW = (const float4*)(W + (size_t)k0 * BN);
#pragma unroll
            for (int u = 0; u < WU; u++) {
                int slot = tid + u * 256;
                rw[u] = srcW[slot];
            }
        }
        __syncthreads();
#pragma unroll
        for (int u = 0; u < 4; u++) {
            int slot = tid + u * 256;
            int r = slot >> 3, c4 = slot & 7;
            float4 v = pf[u];
            __half2 h01 = __floats2half2_rn(v.x, v.y);
            __half2 h23 = __floats2half2_rn(v.z, v.w);
            int o = r * APAD + c4 * 4;
            *(__half2*)&sA[o]     = h01;
            *(__half2*)&sA[o + 2] = h23;
        }
#pragma unroll
        for (int u = 0; u < WU; u++) {
            int slot = tid + u * 256;
            int f = slot * 4;
            int kk = f / BN, n = f % BN;
            float4 v = rw[u];
            __half2 p0 = __floats2half2_rn(v.x, v.y);
            __half2 p1 = __floats2half2_rn(v.z, v.w);
            int o = kk * BPAD + n;
            *(__half2*)&sB[o]     = p0;
            *(__half2*)&sB[o + 2] = p1;
        }
        __syncthreads();
        if (ch + 1 < NCH) {
            const int kn = k0 + CK;
#pragma unroll
            for (int u = 0; u < 4; u++) {
                int slot = tid + u * 256;
                int r = slot >> 3, c4 = slot & 7;
                int m = m0 + r;
                pf[u] = (m < M) ? __ldcs((const float4*)&A[(size_t)m * K + kn + c4 * 4])
                                : make_float4(0.f, 0.f, 0.f, 0.f);
            }
        }
#pragma unroll
        for (int ks = 0; ks < 2; ks++) {
            wmma::fragment<wmma::matrix_a, 16, 16, 16, __half, wmma::row_major> af[2];
#pragma unroll
            for (int i = 0; i < 2; i++) {
                int ro = (warp_m * 32 + i * 16) * APAD + ks * 16;
                wmma::load_matrix_sync(af[i], &sA[ro], APAD);
            }
#pragma unroll
            for (int j = 0; j < NF; j++) {
                wmma::fragment<wmma::matrix_b, 16, 16, 16, __half, wmma::row_major> bf;
                int col = warp_n * (BN / 2) + j * 16;
                wmma::load_matrix_sync(bf, &sB[(ks * 16) * BPAD + col], BPAD);
#pragma unroll
                for (int i = 0; i < 2; i++)
                    wmma::mma_sync(acc[i][j], af[i], bf, acc[i][j]);
            }
        }
    }

    __syncthreads();
    float* st = sStage + wid * 16 * 20;
    const int r  = lane >> 1;
    const int hf = lane & 1;
#pragma unroll
    for (int i = 0; i < 2; i++) {
#pragma unroll
        for (int j = 0; j < NF; j++) {
            wmma::store_matrix_sync(st, acc[i][j], 20, wmma::mem_row_major);
            __syncwarp();
            const float* p = st + r * 20 + hf * 8;
            __half2 a0 = __floats2half2_rn(p[0], p[1]);
            __half2 a1 = __floats2half2_rn(p[2], p[3]);
            __half2 a2 = __floats2half2_rn(p[4], p[5]);
            __half2 a3 = __floats2half2_rn(p[6], p[7]);
            uint4 o;
            o.x = *(unsigned int*)&a0; o.y = *(unsigned int*)&a1;
            o.z = *(unsigned int*)&a2; o.w = *(unsigned int*)&a3;
            int row = m0 + warp_m * 32 + i * 16 + r;
            int col = warp_n * (BN / 2) + j * 16 + hf * 8;
            *(uint4*)&Ch[(size_t)row * BN + col] = o;
            __syncwarp();
        }
    }
}

// -------------------- helpers for aggregation --------------------------------
__device__ __forceinline__ void fma_h4(float4& a, float wt, uint2 v) {
    __half2 p0 = *reinterpret_cast<__half2*>(&v.x);
    __half2 p1 = *reinterpret_cast<__half2*>(&v.y);
    float2 f0 = __half22float2(p0);
    float2 f1 = __half22float2(p1);
    a.x = fmaf(wt, f0.x, a.x);
    a.y = fmaf(wt, f0.y, a.y);
    a.z = fmaf(wt, f1.x, a.z);
    a.w = fmaf(wt, f1.y, a.w);
}

// ---------- FUSED agg1 + gemm2: x1 = relu(agg(sup1)+b1); sup2 = x1@W2 --------
// CTA = 128 rows. Phase A: 8 warps x 16 contiguous rows aggregate (MLP-8),
// write x1 fp32 to gmem AND fp16 into smem. Phase B: 128x64x128 MMA from smem.
#define XPAD 136
#define BPAD2 72
#define FUSED_SMEM (128 * XPAD * 2 + 128 * BPAD2 * 2)

__global__ void __launch_bounds__(256, 2)
agg1_gemm2_k(const float* __restrict__ b1, const float* __restrict__ W2,
             float* __restrict__ x1, int N) {
    extern __shared__ char dyn[];
    __half* sX = (__half*)dyn;                 // 128 x XPAD halves
    __half* sB = sX + 128 * XPAD;              // 128 x BPAD2 halves
    float* sStage = (float*)dyn;               // epilogue reuse (sX dead then)

    const int tid  = threadIdx.x;
    const int wid  = tid >> 5;
    const int lane = tid & 31;
    const int m0   = blockIdx.x * 128;

    // ---- stage W2 (128x64 fp32 -> fp16 smem); no sync needed until phase B --
#pragma unroll
    for (int u = 0; u < 8; u++) {
        int slot = tid + u * 256;              // 2048 float4 slots
        int f = slot * 4;
        int kk = f >> 6, n = f & 63;
        float4 v = __ldg(&((const float4*)W2)[slot]);
        __half2 p0 = __floats2half2_rn(v.x, v.y);
        __half2 p1 = __floats2half2_rn(v.z, v.w);
        int o = kk * BPAD2 + n;
        *(__half2*)&sB[o]     = p0;
        *(__half2*)&sB[o + 2] = p1;
    }

    // ---- phase A: aggregate 16 contiguous rows per warp ----
    const uint2* S = (const uint2*)g_sup1h;
    float4 bb = ((const float4*)b1)[lane];
    for (int rr = 0; rr < 16; rr++) {
        int rloc = wid * 16 + rr;
        int row  = m0 + rloc;
        float4 a0 = make_float4(0.f, 0.f, 0.f, 0.f);
        float4 a1 = make_float4(0.f, 0.f, 0.f, 0.f);
        if (row < N) {
            int beg = g_rowptr[row];
            int cnt = g_deg[row];
            int i = 0;
            for (; i + 8 <= cnt; i += 8) {
                int2 e[8];
#pragma unroll
                for (int j = 0; j < 8; j++) e[j] = __ldg(&g_epk[beg + i + j]);
                uint2 v[8];
#pragma unroll
                for (int j = 0; j < 8; j++) v[j] = __ldg(&S[(size_t)e[j].x * 32 + lane]);
#pragma unroll
                for (int j = 0; j < 8; j++) {
                    float wt = __int_as_float(e[j].y);
                    fma_h4((j & 1) ? a1 : a0, wt, v[j]);
                }
            }
            for (; i < cnt; i++) {
                int2 ep  = __ldg(&g_epk[beg + i]);
                float wt = __int_as_float(ep.y);
                uint2 v  = __ldg(&S[(size_t)ep.x * 32 + lane]);
                fma_h4(a0, wt, v);
            }
        }
        a0.x = fmaxf(a0.x + a1.x + bb.x, 0.f);
        a0.y = fmaxf(a0.y + a1.y + bb.y, 0.f);
        a0.z = fmaxf(a0.z + a1.z + bb.z, 0.f);
        a0.w = fmaxf(a0.w + a1.w + bb.w, 0.f);
        if (row < N)
            __stcs(&((float4*)x1)[(size_t)row * 32 + lane], a0);
        // fp16 copy into smem (also for pad rows: zeros, keeps MMA clean)
        __half2 h01 = __floats2half2_rn(a0.x, a0.y);
        __half2 h23 = __floats2half2_rn(a0.z, a0.w);
        int o = rloc * XPAD + lane * 4;
        *(__half2*)&sX[o]     = h01;
        *(__half2*)&sX[o + 2] = h23;
    }
    __syncthreads();

    // ---- phase B: 128x64x128 MMA from smem ----
    const int warp_m = wid >> 1;
    const int warp_n = wid & 1;
    wmma::fragment<wmma::accumulator, 16, 16, 16, float> acc[2][2];
#pragma unroll
    for (int i = 0; i < 2; i++)
#pragma unroll
        for (int j = 0; j < 2; j++) wmma::fill_fragment(acc[i][j], 0.0f);

#pragma unroll
    for (int ks = 0; ks < 8; ks++) {
        wmma::fragment<wmma::matrix_a, 16, 16, 16, __half, wmma::row_major> af[2];
#pragma unroll
        for (int i = 0; i < 2; i++) {
            int ro = (warp_m * 32 + i * 16) * XPAD + ks * 16;
            wmma::load_matrix_sync(af[i], &sX[ro], XPAD);
        }
#pragma unroll
        for (int j = 0; j < 2; j++) {
            wmma::fragment<wmma::matrix_b, 16, 16, 16, __half, wmma::row_major> bf;
            int col = warp_n * 32 + j * 16;
            wmma::load_matrix_sync(bf, &sB[(ks * 16) * BPAD2 + col], BPAD2);
#pragma unroll
            for (int i = 0; i < 2; i++)
                wmma::mma_sync(acc[i][j], af[i], bf, acc[i][j]);
        }
    }

    // ---- epilogue: acc -> stage (sX region) -> fp16 gmem (padded rows) ----
    __syncthreads();
    float* st = sStage + wid * 16 * 20;
    const int r  = lane >> 1;
    const int hf = lane & 1;
    __half* Ch = g_sup2h;
#pragma unroll
    for (int i = 0; i < 2; i++) {
#pragma unroll
        for (int j = 0; j < 2; j++) {
            wmma::store_matrix_sync(st, acc[i][j], 20, wmma::mem_row_major);
            __syncwarp();
            const float* p = st + r * 20 + hf * 8;
            __half2 a0 = __floats2half2_rn(p[0], p[1]);
            __half2 a1 = __floats2half2_rn(p[2], p[3]);
            __half2 a2 = __floats2half2_rn(p[4], p[5]);
            __half2 a3 = __floats2half2_rn(p[6], p[7]);
            uint4 o;
            o.x = *(unsigned int*)&a0; o.y = *(unsigned int*)&a1;
            o.z = *(unsigned int*)&a2; o.w = *(unsigned int*)&a3;
            int row = m0 + warp_m * 32 + i * 16 + r;
            int col = warp_n * 32 + j * 16 + hf * 8;
            *(uint4*)&Ch[(size_t)row * 64 + col] = o;
            __syncwarp();
        }
    }
}

// layer 2: out = log_softmax(A_hat @ sup2h + b2); 8-wide batches, dual accums
__global__ void agg2_k(const float* __restrict__ b2, float* __restrict__ out, int N) {
    int row  = (blockIdx.x * blockDim.x + threadIdx.x) >> 5;
    int lane = threadIdx.x & 31;
    if (row >= N) return;
    int beg = g_rowptr[row];
    int cnt = g_deg[row];
    float ax0 = 0.f, ay0 = 0.f, ax1 = 0.f, ay1 = 0.f;
    const __half2* S = (const __half2*)g_sup2h;
    int i = 0;
    for (; i + 8 <= cnt; i += 8) {
        int2 e[8];
#pragma unroll
        for (int j = 0; j < 8; j++) e[j] = __ldcs(&g_epk[beg + i + j]);
        __half2 v[8];
#pragma unroll
        for (int j = 0; j < 8; j++) v[j] = __ldg(&S[(size_t)e[j].x * 32 + lane]);
#pragma unroll
        for (int j = 0; j < 8; j++) {
            float wt = __int_as_float(e[j].y);
            float2 f = __half22float2(v[j]);
            if (j & 1) { ax1 = fmaf(wt, f.x, ax1); ay1 = fmaf(wt, f.y, ay1); }
            else       { ax0 = fmaf(wt, f.x, ax0); ay0 = fmaf(wt, f.y, ay0); }
        }
    }
    for (; i < cnt; i++) {
        int2 ep  = __ldg(&g_epk[beg + i]);
        float wt = __int_as_float(ep.y);
        float2 f = __half22float2(__ldg(&S[(size_t)ep.x * 32 + lane]));
        ax0 = fmaf(wt, f.x, ax0);
        ay0 = fmaf(wt, f.y, ay0);
    }
    float ax = ax0 + ax1, ay = ay0 + ay1;
    float2 bb = ((const float2*)b2)[lane];
    ax += bb.x;
    ay += bb.y;
    float m = fmaxf(ax, ay);
#pragma unroll
    for (int off = 16; off > 0; off >>= 1)
        m = fmaxf(m, __shfl_xor_sync(0xffffffffu, m, off));
    float se = expf(ax - m) + expf(ay - m);
#pragma unroll
    for (int off = 16; off > 0; off >>= 1)
        se += __shfl_xor_sync(0xffffffffu, se, off);
    float ls = logf(se);
    float2 o;
    o.x = ax - m - ls;
    o.y = ay - m - ls;
    __stcs(&((float2*)out)[(size_t)row * 32 + lane], o);
}

// ------------------------------ launcher ------------------------------------
// Streams/events are process-lifetime resources, created once on the FIRST
// call (pre-baseline) and reused. The enqueued kernel DAG is identical on
// every call; the captured graph never allocates.
extern "C" void kernel_launch(void* const* d_in, const int* in_sizes, int n_in,
                              void* d_out, int out_size) {
    const float* feature = (const float*)d_in[0];
    const int*   src     = (const int*)d_in[1];
    const int*   dst     = (const int*)d_in[2];
    const float* ew      = (const float*)d_in[3];
    const float* W1      = (const float*)d_in[4];
    const float* b1      = (const float*)d_in[5];
    const float* W2      = (const float*)d_in[6];
    const float* b2      = (const float*)d_in[7];

    const int E = in_sizes[1];
    const int H = in_sizes[5];            // 128
    const int F = in_sizes[4] / H;        // 256
    const int N = in_sizes[0] / F;        // 100000

    float* x1   = (float*)d_out;                        // output[0]: [N, 128]
    float* out2 = (float*)d_out + (size_t)N * H;        // output[1]: [N, 64]

    __half* sup1 = nullptr;
    cudaGetSymbolAddress((void**)&sup1, g_sup1h);

    const int nblk = (N + 127) / 128;
    const int nchunk = (N + 1023) / 1024;

    // one-time resource setup (first call = correctness run, pre-baseline)
    static cudaStream_t s1 = nullptr, s2 = nullptr;
    static cudaEvent_t evRoot = nullptr, evCsr = nullptr, evGemm = nullptr;
    if (s1 == nullptr) {
        cudaStreamCreateWithFlags(&s1, cudaStreamNonBlocking);
        cudaStreamCreateWithFlags(&s2, cudaStreamNonBlocking);
        cudaEventCreateWithFlags(&evRoot, cudaEventDisableTiming);
        cudaEventCreateWithFlags(&evCsr,  cudaEventDisableTiming);
        cudaEventCreateWithFlags(&evGemm, cudaEventDisableTiming);
        cudaFuncSetAttribute(agg1_gemm2_k,
                             cudaFuncAttributeMaxDynamicSharedMemorySize, FUSED_SMEM);
    }

    // ---- fork: fused CSR (s1) || GEMM1 (s2) ----
    cudaEventRecord(evRoot, 0);
    cudaStreamWaitEvent(s1, evRoot, 0);
    cudaStreamWaitEvent(s2, evRoot, 0);

    csr_fused_k<<<CSR_BLOCKS, 256, 0, s1>>>(src, dst, ew, E, N, nchunk);
    cudaEventRecord(evCsr, s1);

    gemm_wmma_k<128, 256><<<nblk, 256, 0, s2>>>(feature, W1, sup1, N);
    cudaEventRecord(evGemm, s2);

    // join on default stream
    cudaStreamWaitEvent(0, evCsr, 0);
    cudaStreamWaitEvent(0, evGemm, 0);

    // ---- fused layer-1 aggregation + layer-2 GEMM, then layer-2 agg ----
    agg1_gemm2_k<<<nblk, 256, FUSED_SMEM>>>(b1, W2, x1, N);
    agg2_k<<<((size_t)N * 32 + 255) / 256, 256>>>(b2, out2, N);
}